// round 15
// baseline (speedup 1.0000x reference)
#include <cuda_runtime.h>
#include <cuda_bf16.h>
#include <cstdint>

#define D 128
#define MAXN 100000
#define MAXE 1000000
#define SCAN_B 256
#define MAXBLK ((MAXN + SCAN_B - 1) / SCAN_B)
#define BKW 68                 // B row stride in 32-bit words (64 data + 4 pad)
#define AGG_BLOCKS 592         // 148 SMs x 4 resident blocks (guaranteed one wave)

// ---------------- device scratch ----------------
__device__ __align__(16) float g_h[(size_t)MAXN * D];     // raw h = x@W
__device__ __align__(16) float g_agg[(size_t)MAXN * D];   // b + relu(res), then final y
__device__ __align__(16) float g_dinv[MAXN];
__device__ __align__(16) float g_sum[D];
__device__ __align__(16) float g_sumsq[D];
__device__ int g_cnt[MAXN];
__device__ int g_roff[MAXN + 1];
__device__ int g_wcur[MAXN];
__device__ int g_srcs[MAXE];
__device__ int g_bsum[MAXBLK];
__device__ int g_is64;
__device__ unsigned int g_barrier;

__device__ __forceinline__ int ld_idx(const int* __restrict__ ei32, size_t pos, int is64) {
    return is64 ? ei32[pos << 1] : ei32[pos];
}
__device__ __forceinline__ uint32_t pack2(float a, float b) {
    __nv_bfloat162 t = __floats2bfloat162_rn(a, b);
    return *reinterpret_cast<uint32_t*>(&t);
}
__device__ __forceinline__ float bf16_hi(float v) {
    return __bfloat162float(__float2bfloat16(v));
}
__device__ __forceinline__ void mma_bf16(float* c, const uint32_t* a, uint32_t b0, uint32_t b1) {
    asm volatile(
        "mma.sync.aligned.m16n8k16.row.col.f32.bf16.bf16.f32 "
        "{%0,%1,%2,%3}, {%4,%5,%6,%7}, {%8,%9}, {%0,%1,%2,%3};"
        : "+f"(c[0]), "+f"(c[1]), "+f"(c[2]), "+f"(c[3])
        : "r"(a[0]), "r"(a[1]), "r"(a[2]), "r"(a[3]), "r"(b0), "r"(b1));
}

// ---------------- K_zero (s2): init counters/sums + dtype-detect ----------------
__global__ void k_zero(const int* __restrict__ ei32, int E, int N) {
    int i = blockIdx.x * blockDim.x + threadIdx.x;
    if (i < N) g_cnt[i] = 0;
    if (i < D) { g_sum[i] = 0.0f; g_sumsq[i] = 0.0f; }
    if (i == 0) { g_is64 = 1; g_barrier = 0u; }
    __threadfence();
    if (i < E && i < 1024) {
        if (ei32[2 * i + 1] != 0) g_is64 = 0;
    }
}

// ---------------- CSR build ----------------
__global__ void k_hist(const int* __restrict__ ei32, int E) {
    int e = blockIdx.x * blockDim.x + threadIdx.x;
    if (e >= E) return;
    int is64 = g_is64;
    atomicAdd(&g_cnt[ld_idx(ei32, (size_t)E + e, is64)], 1);
}

__global__ void __launch_bounds__(SCAN_B) k_scan1(int N) {
    __shared__ int red[SCAN_B / 32];
    int i = blockIdx.x * SCAN_B + threadIdx.x;
    int v = (i < N) ? g_cnt[i] : 0;
    #pragma unroll
    for (int o = 16; o > 0; o >>= 1) v += __shfl_down_sync(0xffffffff, v, o);
    int warp = threadIdx.x >> 5, lane = threadIdx.x & 31;
    if (lane == 0) red[warp] = v;
    __syncthreads();
    if (warp == 0) {
        int s = (lane < SCAN_B / 32) ? red[lane] : 0;
        #pragma unroll
        for (int o = 4; o > 0; o >>= 1) s += __shfl_down_sync(0xffffffff, s, o);
        if (lane == 0) g_bsum[blockIdx.x] = s;
    }
}

__global__ void __launch_bounds__(1024) k_scan2(int nblk, int N) {
    __shared__ int sh[1024];
    int t = threadIdx.x;
    int v = (t < nblk) ? g_bsum[t] : 0;
    sh[t] = v;
    __syncthreads();
    for (int off = 1; off < 1024; off <<= 1) {
        int u = (t >= off) ? sh[t - off] : 0;
        __syncthreads();
        sh[t] += u;
        __syncthreads();
    }
    if (t < nblk) g_bsum[t] = sh[t] - v;
    if (t == 0) g_roff[N] = sh[1023];
}

__global__ void __launch_bounds__(SCAN_B) k_scan3(int N) {
    __shared__ int wsum[SCAN_B / 32];
    int i = blockIdx.x * SCAN_B + threadIdx.x;
    int c = (i < N) ? g_cnt[i] : 0;
    int lane = threadIdx.x & 31, warp = threadIdx.x >> 5;
    int s = c;
    #pragma unroll
    for (int o = 1; o < 32; o <<= 1) {
        int u = __shfl_up_sync(0xffffffff, s, o);
        if (lane >= o) s += u;
    }
    if (lane == 31) wsum[warp] = s;
    __syncthreads();
    if (warp == 0) {
        int w = (lane < SCAN_B / 32) ? wsum[lane] : 0;
        #pragma unroll
        for (int o = 1; o < SCAN_B / 32; o <<= 1) {
            int u = __shfl_up_sync(0xffffffff, w, o);
            if (lane >= o) w += u;
        }
        if (lane < SCAN_B / 32) wsum[lane] = w;
    }
    __syncthreads();
    int excl = s - c + (warp > 0 ? wsum[warp - 1] : 0) + g_bsum[blockIdx.x];
    if (i < N) {
        g_roff[i] = excl;
        g_wcur[i] = excl;
        g_dinv[i] = rsqrtf((float)c + 1.0f);
    }
}

__global__ void k_fill(const int* __restrict__ ei32, int E) {
    int e = blockIdx.x * blockDim.x + threadIdx.x;
    if (e >= E) return;
    int is64 = g_is64;
    int s = ld_idx(ei32, (size_t)e, is64);
    int d = ld_idx(ei32, (size_t)E + e, is64);
    g_srcs[atomicAdd(&g_wcur[d], 1)] = s;
}

// ---------------- persistent mma.sync fused dual GEMM (zero dependencies) ----------------
// Tile: 128 rows x 256 cols; 8 warps: wr = wid&3 (32-row band, TWO m16 frags
// sharing each B load), wc = wid>>2 (128-col half). bf16x3 split, K=128.
// B hi/lo smem images built IN-KERNEL from W/res_W (no setup dependency).
// Writes RAW h and agg0 = b + relu(res). NO degree dependency.
#define S_BHI 0
#define S_BLO 69632
#define S_STAGE 139264          // float stage[128][136]
#define SMEM_MMA (S_STAGE + 128 * 136 * 4)

__global__ void __launch_bounds__(256, 1) k_gemm_mma(
    const float* __restrict__ x, const float* __restrict__ W,
    const float* __restrict__ rW, const float* __restrict__ b,
    const float* __restrict__ rb, int N, int ntiles)
{
    extern __shared__ char smem[];
    uint32_t* sBhi = (uint32_t*)(smem + S_BHI);
    uint32_t* sBlo = (uint32_t*)(smem + S_BLO);
    float* stage = (float*)(smem + S_STAGE);

    const int tid = threadIdx.x;
    const int wid = tid >> 5, lane = tid & 31;
    const int wr = wid & 3, wc = wid >> 2;
    const int g = lane >> 2, tg = lane & 3;

    // ---- build B hi/lo images in smem directly from W / res_W ----
    // thread tid owns output column n = tid (n<128 -> W col n, else res_W col n-128)
    {
        const int n = tid;
        const float* src = (n < 128) ? W : rW;
        const int col = n & 127;
        #pragma unroll 4
        for (int kw = 0; kw < 64; kw++) {
            float v0 = src[(size_t)(2 * kw) * D + col];      // coalesced across lanes
            float v1 = src[(size_t)(2 * kw + 1) * D + col];
            float h0 = bf16_hi(v0), h1 = bf16_hi(v1);
            sBhi[n * BKW + kw] = pack2(v0, v1);
            sBlo[n * BKW + kw] = pack2(v0 - h0, v1 - h1);
        }
        #pragma unroll
        for (int kw = 64; kw < BKW; kw++) {
            sBhi[n * BKW + kw] = 0;
            sBlo[n * BKW + kw] = 0;
        }
    }
    __syncthreads();

    for (int tile = blockIdx.x; tile < ntiles; tile += gridDim.x) {
        __syncthreads();

        const int base = tile * 128 + wr * 32;
        const int rA0 = base + g,      rA1 = base + 8 + g;
        const int rB0 = base + 16 + g, rB1 = base + 24 + g;
        const bool okA0 = rA0 < N, okA1 = rA1 < N, okB0 = rB0 < N, okB1 = rB1 < N;
        const float* xA0 = x + (size_t)rA0 * D;
        const float* xA1 = x + (size_t)rA1 * D;
        const float* xB0 = x + (size_t)rB0 * D;
        const float* xB1 = x + (size_t)rB1 * D;

        float c0[16][4], c1[16][4];
        #pragma unroll
        for (int i = 0; i < 16; i++)
            #pragma unroll
            for (int j = 0; j < 4; j++) { c0[i][j] = 0.f; c1[i][j] = 0.f; }

        #pragma unroll
        for (int ks = 0; ks < 8; ks++) {
            int k0 = ks * 16 + tg * 2;
            float2 z = make_float2(0.f, 0.f);
            float2 a00 = okA0 ? *(const float2*)(xA0 + k0)     : z;
            float2 a10 = okA1 ? *(const float2*)(xA1 + k0)     : z;
            float2 a01 = okA0 ? *(const float2*)(xA0 + k0 + 8) : z;
            float2 a11 = okA1 ? *(const float2*)(xA1 + k0 + 8) : z;
            float2 b00 = okB0 ? *(const float2*)(xB0 + k0)     : z;
            float2 b10 = okB1 ? *(const float2*)(xB1 + k0)     : z;
            float2 b01 = okB0 ? *(const float2*)(xB0 + k0 + 8) : z;
            float2 b11 = okB1 ? *(const float2*)(xB1 + k0 + 8) : z;
            uint32_t ahi0[4], alo0[4], ahi1[4], alo1[4];
            ahi0[0] = pack2(a00.x, a00.y); ahi0[1] = pack2(a10.x, a10.y);
            ahi0[2] = pack2(a01.x, a01.y); ahi0[3] = pack2(a11.x, a11.y);
            alo0[0] = pack2(a00.x - bf16_hi(a00.x), a00.y - bf16_hi(a00.y));
            alo0[1] = pack2(a10.x - bf16_hi(a10.x), a10.y - bf16_hi(a10.y));
            alo0[2] = pack2(a01.x - bf16_hi(a01.x), a01.y - bf16_hi(a01.y));
            alo0[3] = pack2(a11.x - bf16_hi(a11.x), a11.y - bf16_hi(a11.y));
            ahi1[0] = pack2(b00.x, b00.y); ahi1[1] = pack2(b10.x, b10.y);
            ahi1[2] = pack2(b01.x, b01.y); ahi1[3] = pack2(b11.x, b11.y);
            alo1[0] = pack2(b00.x - bf16_hi(b00.x), b00.y - bf16_hi(b00.y));
            alo1[1] = pack2(b10.x - bf16_hi(b10.x), b10.y - bf16_hi(b10.y));
            alo1[2] = pack2(b01.x - bf16_hi(b01.x), b01.y - bf16_hi(b01.y));
            alo1[3] = pack2(b11.x - bf16_hi(b11.x), b11.y - bf16_hi(b11.y));

            #pragma unroll
            for (int nt = 0; nt < 16; nt++) {
                int nrow = wc * 128 + nt * 8 + g;
                int w0 = nrow * BKW + ks * 8 + tg;
                uint32_t b0h = sBhi[w0], b1h = sBhi[w0 + 4];
                uint32_t b0l = sBlo[w0], b1l = sBlo[w0 + 4];
                mma_bf16(c0[nt], ahi0, b0h, b1h);
                mma_bf16(c0[nt], ahi0, b0l, b1l);
                mma_bf16(c0[nt], alo0, b0h, b1h);
                mma_bf16(c1[nt], ahi1, b0h, b1h);
                mma_bf16(c1[nt], ahi1, b0l, b1l);
                mma_bf16(c1[nt], alo1, b0h, b1h);
            }
        }

        int lr = wr * 32 + g;
        if (wc == 1) {   // residual half: stage relu(val + rb)
            #pragma unroll
            for (int nt = 0; nt < 16; nt++) {
                int col = nt * 8 + tg * 2;
                float rb0 = rb[col], rb1 = rb[col + 1];
                stage[(lr)      * 136 + col]     = fmaxf(c0[nt][0] + rb0, 0.f);
                stage[(lr)      * 136 + col + 1] = fmaxf(c0[nt][1] + rb1, 0.f);
                stage[(lr + 8)  * 136 + col]     = fmaxf(c0[nt][2] + rb0, 0.f);
                stage[(lr + 8)  * 136 + col + 1] = fmaxf(c0[nt][3] + rb1, 0.f);
                stage[(lr + 16) * 136 + col]     = fmaxf(c1[nt][0] + rb0, 0.f);
                stage[(lr + 16) * 136 + col + 1] = fmaxf(c1[nt][1] + rb1, 0.f);
                stage[(lr + 24) * 136 + col]     = fmaxf(c1[nt][2] + rb0, 0.f);
                stage[(lr + 24) * 136 + col + 1] = fmaxf(c1[nt][3] + rb1, 0.f);
            }
        }
        __syncthreads();
        if (wc == 0) {   // main half: store raw h + agg0 = b + relu(res)
            #pragma unroll
            for (int nt = 0; nt < 16; nt++) {
                int col = nt * 8 + tg * 2;
                float2 bb = *(const float2*)(b + col);
                #pragma unroll
                for (int f = 0; f < 4; f++) {
                    int r = (f == 0) ? rA0 : (f == 1) ? rA1 : (f == 2) ? rB0 : rB1;
                    bool ok = (f == 0) ? okA0 : (f == 1) ? okA1 : (f == 2) ? okB0 : okB1;
                    if (!ok) continue;
                    const float* cc = (f < 2) ? c0[nt] : c1[nt];
                    float v0 = (f & 1) ? cc[2] : cc[0];
                    float v1 = (f & 1) ? cc[3] : cc[1];
                    int srow = lr + ((f & 1) ? 8 : 0) + ((f >> 1) ? 16 : 0);
                    float2 hv, ag;
                    hv.x = v0; hv.y = v1;
                    ag.x = bb.x + stage[srow * 136 + col];
                    ag.y = bb.y + stage[srow * 136 + col + 1];
                    *(float2*)(g_h   + (size_t)r * D + col) = hv;
                    *(float2*)(g_agg + (size_t)r * D + col) = ag;
                }
            }
        }
    }
}

// ---------------- fused: CSR aggregate + BN stats + grid-sync + normalize ----------------
__global__ void __launch_bounds__(256, 4) k_aggnorm(
    const float* __restrict__ gamma, const float* __restrict__ beta,
    float* __restrict__ out, int N, int nwarps)
{
    __shared__ float ss[8][128];
    __shared__ float sq[8][128];
    __shared__ float ssc[128], ssh[128];
    int wid = threadIdx.x >> 5, lane = threadIdx.x & 31;
    int gw = blockIdx.x * 8 + wid;
    float4 bs = make_float4(0.f, 0.f, 0.f, 0.f);
    float4 bq = make_float4(0.f, 0.f, 0.f, 0.f);

    for (int d = gw; d < N; d += nwarps) {
        int beg = g_roff[d], end = g_roff[d + 1];
        float di = g_dinv[d];
        float4 hd = *(const float4*)(g_h + (size_t)d * D + lane * 4);
        float4 acc;
        acc.x = di * hd.x; acc.y = di * hd.y; acc.z = di * hd.z; acc.w = di * hd.w;
        for (int j = beg; j < end; j++) {
            int s = g_srcs[j];
            float ds = g_dinv[s];
            float4 u = *(const float4*)(g_h + (size_t)s * D + lane * 4);
            acc.x += ds * u.x; acc.y += ds * u.y;
            acc.z += ds * u.z; acc.w += ds * u.w;
        }
        float4* ap = (float4*)(g_agg + (size_t)d * D + lane * 4);
        float4 v = *ap;
        v.x += acc.x * di; v.y += acc.y * di;
        v.z += acc.z * di; v.w += acc.w * di;
        *ap = v;
        bs.x += v.x; bs.y += v.y; bs.z += v.z; bs.w += v.w;
        bq.x += v.x * v.x; bq.y += v.y * v.y;
        bq.z += v.z * v.z; bq.w += v.w * v.w;
    }
    *(float4*)&ss[wid][lane * 4] = bs;
    *(float4*)&sq[wid][lane * 4] = bq;
    __syncthreads();
    int col = threadIdx.x & 127;
    if (threadIdx.x < 128) {
        float s = 0.f;
        #pragma unroll
        for (int w = 0; w < 8; w++) s += ss[w][col];
        atomicAdd(&g_sum[col], s);
    } else {
        float s = 0.f;
        #pragma unroll
        for (int w = 0; w < 8; w++) s += sq[w][col];
        atomicAdd(&g_sumsq[col], s);
    }
    __threadfence();
    __syncthreads();

    // ---- grid barrier (all blocks resident by construction) ----
    if (threadIdx.x == 0) {
        atomicAdd(&g_barrier, 1u);
        while (*((volatile unsigned int*)&g_barrier) < (unsigned int)gridDim.x) { }
    }
    __syncthreads();
    __threadfence();

    // ---- BN finalize (per block) ----
    if (threadIdx.x < 128) {
        float inv_n = 1.0f / (float)N;
        float mean = g_sum[threadIdx.x] * inv_n;
        float var = fmaxf(g_sumsq[threadIdx.x] * inv_n - mean * mean, 0.0f);
        float sc = rsqrtf(var + 1e-5f) * gamma[threadIdx.x];
        ssc[threadIdx.x] = sc;
        ssh[threadIdx.x] = beta[threadIdx.x] - mean * sc;
    }
    __syncthreads();

    // ---- normalize the same rows (L2-hot) ----
    float4 sc0 = *(const float4*)&ssc[lane * 4];
    float4 sh0 = *(const float4*)&ssh[lane * 4];
    for (int d = gw; d < N; d += nwarps) {
        float4 v = *(const float4*)(g_agg + (size_t)d * D + lane * 4);
        float4 o;
        o.x = v.x * sc0.x + sh0.x;
        o.y = v.y * sc0.y + sh0.y;
        o.z = v.z * sc0.z + sh0.z;
        o.w = v.w * sc0.w + sh0.w;
        *(float4*)(out + (size_t)d * D + lane * 4) = o;
    }
}

extern "C" void kernel_launch(void* const* d_in, const int* in_sizes, int n_in,
                              void* d_out, int out_size) {
    const float* x     = (const float*)d_in[0];
    const int*   ei32  = (const int*)d_in[1];
    const float* W     = (const float*)d_in[2];
    const float* b     = (const float*)d_in[3];
    const float* rW    = (const float*)d_in[4];
    const float* rb    = (const float*)d_in[5];
    const float* gamma = (const float*)d_in[6];
    const float* beta  = (const float*)d_in[7];
    float* out = (float*)d_out;

    int N = in_sizes[0] / D;
    int E = in_sizes[1] / 2;
    int nblk = (N + SCAN_B - 1) / SCAN_B;
    int ntiles = (N + 127) / 128;
    int gemm_grid = ntiles < 148 ? ntiles : 148;

    cudaFuncSetAttribute(k_gemm_mma, cudaFuncAttributeMaxDynamicSharedMemorySize, SMEM_MMA);

    cudaStream_t s2;
    cudaStreamCreateWithFlags(&s2, cudaStreamNonBlocking);
    cudaEvent_t evFork, evJoin;
    cudaEventCreateWithFlags(&evFork, cudaEventDisableTiming);
    cudaEventCreateWithFlags(&evJoin, cudaEventDisableTiming);

    // fork at t=0: GEMM on main (no dependencies), full CSR build on s2
    cudaEventRecord(evFork, 0);
    cudaStreamWaitEvent(s2, evFork, 0);

    k_zero<<<(N + 255) / 256, 256, 0, s2>>>(ei32, E, N);
    k_hist<<<(E + 255) / 256, 256, 0, s2>>>(ei32, E);
    k_scan1<<<nblk, SCAN_B, 0, s2>>>(N);
    k_scan2<<<1, 1024, 0, s2>>>(nblk, N);
    k_scan3<<<nblk, SCAN_B, 0, s2>>>(N);
    k_fill<<<(E + 255) / 256, 256, 0, s2>>>(ei32, E);
    cudaEventRecord(evJoin, s2);

    k_gemm_mma<<<gemm_grid, 256, SMEM_MMA>>>(x, W, rW, b, rb, N, ntiles);

    cudaStreamWaitEvent(0, evJoin, 0);
    k_aggnorm<<<AGG_BLOCKS, 256>>>(gamma, beta, out, N, AGG_BLOCKS * 8);

    cudaEventDestroy(evFork);
    cudaEventDestroy(evJoin);
    cudaStreamDestroy(s2);
}

// round 16
// speedup vs baseline: 1.0829x; 1.0829x over previous
#include <cuda_runtime.h>
#include <cuda_bf16.h>
#include <cuda_fp16.h>
#include <cstdint>

#define D 128
#define MAXN 100000
#define MAXE 1000000
#define SCAN_B 256
#define MAXBLK ((MAXN + SCAN_B - 1) / SCAN_B)
#define BKW 68                 // B row stride in 32-bit words (64 data + 4 pad)
#define AGG_BLOCKS 592         // 148 SMs x 4 resident blocks (guaranteed one wave)

// ---------------- device scratch ----------------
__device__ __align__(16) uint32_t g_h16[(size_t)MAXN * (D / 2)];  // h packed as half2
__device__ __align__(16) float g_agg[(size_t)MAXN * D];   // b + relu(res), then final y
__device__ __align__(16) float g_dinv[MAXN];
__device__ __align__(16) float g_sum[D];
__device__ __align__(16) float g_sumsq[D];
__device__ int g_cnt[MAXN];
__device__ int g_roff[MAXN + 1];
__device__ int g_wcur[MAXN];
__device__ int g_srcs[MAXE];
__device__ int g_bsum[MAXBLK];
__device__ int g_is64;
__device__ unsigned int g_barrier;
// B operand images: [n=256][kword=68] bf16x2 words; n<128 -> W col n, else res_W col n-128
__device__ __align__(16) uint32_t g_Bw_hi[256 * BKW];
__device__ __align__(16) uint32_t g_Bw_lo[256 * BKW];

__device__ __forceinline__ int ld_idx(const int* __restrict__ ei32, size_t pos, int is64) {
    return is64 ? ei32[pos << 1] : ei32[pos];
}
__device__ __forceinline__ uint32_t pack2(float a, float b) {
    __nv_bfloat162 t = __floats2bfloat162_rn(a, b);
    return *reinterpret_cast<uint32_t*>(&t);
}
__device__ __forceinline__ uint32_t packh2(float a, float b) {
    __half2 t = __floats2half2_rn(a, b);
    return *reinterpret_cast<uint32_t*>(&t);
}
__device__ __forceinline__ float bf16_hi(float v) {
    return __bfloat162float(__float2bfloat16(v));
}
__device__ __forceinline__ void mma_bf16(float* c, const uint32_t* a, uint32_t b0, uint32_t b1) {
    asm volatile(
        "mma.sync.aligned.m16n8k16.row.col.f32.bf16.bf16.f32 "
        "{%0,%1,%2,%3}, {%4,%5,%6,%7}, {%8,%9}, {%0,%1,%2,%3};"
        : "+f"(c[0]), "+f"(c[1]), "+f"(c[2]), "+f"(c[3])
        : "r"(a[0]), "r"(a[1]), "r"(a[2]), "r"(a[3]), "r"(b0), "r"(b1));
}

// ---------------- K_prep (main): B hi/lo images only (GEMM's sole dependency) ----------------
__global__ void k_prep(const float* __restrict__ W, const float* __restrict__ rW) {
    int t = blockIdx.x * blockDim.x + threadIdx.x;   // 16384 threads
    if (t >= 256 * 64) return;
    int n = t >> 6, kw = t & 63;
    const float* src = (n < 128) ? W : rW;
    int col = n & 127;
    float v0 = src[(size_t)(2 * kw) * D + col];
    float v1 = src[(size_t)(2 * kw + 1) * D + col];
    float h0 = bf16_hi(v0), h1 = bf16_hi(v1);
    g_Bw_hi[n * BKW + kw] = pack2(v0, v1);
    g_Bw_lo[n * BKW + kw] = pack2(v0 - h0, v1 - h1);
    if (kw < 4) { g_Bw_hi[n * BKW + 64 + kw] = 0; g_Bw_lo[n * BKW + 64 + kw] = 0; }
}

// ---------------- K_zero (s2): counters/sums init + dtype-detect ----------------
__global__ void k_zero(const int* __restrict__ ei32, int E, int N) {
    int i = blockIdx.x * blockDim.x + threadIdx.x;
    if (i < N) g_cnt[i] = 0;
    if (i < D) { g_sum[i] = 0.0f; g_sumsq[i] = 0.0f; }
    if (i == 0) { g_is64 = 1; g_barrier = 0u; }
    __threadfence();
    if (i < E && i < 1024) {
        if (ei32[2 * i + 1] != 0) g_is64 = 0;
    }
}

// ---------------- CSR build ----------------
__global__ void k_hist(const int* __restrict__ ei32, int E) {
    int e = blockIdx.x * blockDim.x + threadIdx.x;
    if (e >= E) return;
    int is64 = g_is64;
    atomicAdd(&g_cnt[ld_idx(ei32, (size_t)E + e, is64)], 1);
}

__global__ void __launch_bounds__(SCAN_B) k_scan1(int N) {
    __shared__ int red[SCAN_B / 32];
    int i = blockIdx.x * SCAN_B + threadIdx.x;
    int v = (i < N) ? g_cnt[i] : 0;
    #pragma unroll
    for (int o = 16; o > 0; o >>= 1) v += __shfl_down_sync(0xffffffff, v, o);
    int warp = threadIdx.x >> 5, lane = threadIdx.x & 31;
    if (lane == 0) red[warp] = v;
    __syncthreads();
    if (warp == 0) {
        int s = (lane < SCAN_B / 32) ? red[lane] : 0;
        #pragma unroll
        for (int o = 4; o > 0; o >>= 1) s += __shfl_down_sync(0xffffffff, s, o);
        if (lane == 0) g_bsum[blockIdx.x] = s;
    }
}

__global__ void __launch_bounds__(1024) k_scan2(int nblk, int N) {
    __shared__ int sh[1024];
    int t = threadIdx.x;
    int v = (t < nblk) ? g_bsum[t] : 0;
    sh[t] = v;
    __syncthreads();
    for (int off = 1; off < 1024; off <<= 1) {
        int u = (t >= off) ? sh[t - off] : 0;
        __syncthreads();
        sh[t] += u;
        __syncthreads();
    }
    if (t < nblk) g_bsum[t] = sh[t] - v;
    if (t == 0) g_roff[N] = sh[1023];
}

__global__ void __launch_bounds__(SCAN_B) k_scan3(int N) {
    __shared__ int wsum[SCAN_B / 32];
    int i = blockIdx.x * SCAN_B + threadIdx.x;
    int c = (i < N) ? g_cnt[i] : 0;
    int lane = threadIdx.x & 31, warp = threadIdx.x >> 5;
    int s = c;
    #pragma unroll
    for (int o = 1; o < 32; o <<= 1) {
        int u = __shfl_up_sync(0xffffffff, s, o);
        if (lane >= o) s += u;
    }
    if (lane == 31) wsum[warp] = s;
    __syncthreads();
    if (warp == 0) {
        int w = (lane < SCAN_B / 32) ? wsum[lane] : 0;
        #pragma unroll
        for (int o = 1; o < SCAN_B / 32; o <<= 1) {
            int u = __shfl_up_sync(0xffffffff, w, o);
            if (lane >= o) w += u;
        }
        if (lane < SCAN_B / 32) wsum[lane] = w;
    }
    __syncthreads();
    int excl = s - c + (warp > 0 ? wsum[warp - 1] : 0) + g_bsum[blockIdx.x];
    if (i < N) {
        g_roff[i] = excl;
        g_wcur[i] = excl;
        g_dinv[i] = rsqrtf((float)c + 1.0f);
    }
}

__global__ void k_fill(const int* __restrict__ ei32, int E) {
    int e = blockIdx.x * blockDim.x + threadIdx.x;
    if (e >= E) return;
    int is64 = g_is64;
    int s = ld_idx(ei32, (size_t)e, is64);
    int d = ld_idx(ei32, (size_t)E + e, is64);
    g_srcs[atomicAdd(&g_wcur[d], 1)] = s;
}

// ---------------- persistent mma.sync fused dual GEMM ----------------
// Tile: 128 rows x 256 cols; 8 warps: wr = wid&3 (32-row band, TWO m16 frags
// sharing each B load), wc = wid>>2 (128-col half). bf16x3 split, K=128.
// Writes h packed fp16x2 and agg0 = b + relu(res). Depends only on k_prep.
#define S_BHI 0
#define S_BLO 69632
#define S_STAGE 139264          // float stage[128][136]
#define SMEM_MMA (S_STAGE + 128 * 136 * 4)

__global__ void __launch_bounds__(256, 1) k_gemm_mma(
    const float* __restrict__ x, const float* __restrict__ b,
    const float* __restrict__ rb, int N, int ntiles)
{
    extern __shared__ char smem[];
    uint32_t* sBhi = (uint32_t*)(smem + S_BHI);
    uint32_t* sBlo = (uint32_t*)(smem + S_BLO);
    float* stage = (float*)(smem + S_STAGE);

    const int tid = threadIdx.x;
    const int wid = tid >> 5, lane = tid & 31;
    const int wr = wid & 3, wc = wid >> 2;
    const int g = lane >> 2, tg = lane & 3;

    {
        const uint4* sh = (const uint4*)g_Bw_hi;
        const uint4* sl = (const uint4*)g_Bw_lo;
        uint4* dh = (uint4*)sBhi;
        uint4* dl = (uint4*)sBlo;
        #pragma unroll
        for (int i = 0; i < 17; i++) {
            int idx = tid + i * 256;
            dh[idx] = sh[idx];
            dl[idx] = sl[idx];
        }
    }
    __syncthreads();

    for (int tile = blockIdx.x; tile < ntiles; tile += gridDim.x) {
        __syncthreads();

        const int base = tile * 128 + wr * 32;
        const int rA0 = base + g,      rA1 = base + 8 + g;
        const int rB0 = base + 16 + g, rB1 = base + 24 + g;
        const bool okA0 = rA0 < N, okA1 = rA1 < N, okB0 = rB0 < N, okB1 = rB1 < N;
        const float* xA0 = x + (size_t)rA0 * D;
        const float* xA1 = x + (size_t)rA1 * D;
        const float* xB0 = x + (size_t)rB0 * D;
        const float* xB1 = x + (size_t)rB1 * D;

        float c0[16][4], c1[16][4];
        #pragma unroll
        for (int i = 0; i < 16; i++)
            #pragma unroll
            for (int j = 0; j < 4; j++) { c0[i][j] = 0.f; c1[i][j] = 0.f; }

        #pragma unroll
        for (int ks = 0; ks < 8; ks++) {
            int k0 = ks * 16 + tg * 2;
            float2 z = make_float2(0.f, 0.f);
            float2 a00 = okA0 ? *(const float2*)(xA0 + k0)     : z;
            float2 a10 = okA1 ? *(const float2*)(xA1 + k0)     : z;
            float2 a01 = okA0 ? *(const float2*)(xA0 + k0 + 8) : z;
            float2 a11 = okA1 ? *(const float2*)(xA1 + k0 + 8) : z;
            float2 b00 = okB0 ? *(const float2*)(xB0 + k0)     : z;
            float2 b10 = okB1 ? *(const float2*)(xB1 + k0)     : z;
            float2 b01 = okB0 ? *(const float2*)(xB0 + k0 + 8) : z;
            float2 b11 = okB1 ? *(const float2*)(xB1 + k0 + 8) : z;
            uint32_t ahi0[4], alo0[4], ahi1[4], alo1[4];
            ahi0[0] = pack2(a00.x, a00.y); ahi0[1] = pack2(a10.x, a10.y);
            ahi0[2] = pack2(a01.x, a01.y); ahi0[3] = pack2(a11.x, a11.y);
            alo0[0] = pack2(a00.x - bf16_hi(a00.x), a00.y - bf16_hi(a00.y));
            alo0[1] = pack2(a10.x - bf16_hi(a10.x), a10.y - bf16_hi(a10.y));
            alo0[2] = pack2(a01.x - bf16_hi(a01.x), a01.y - bf16_hi(a01.y));
            alo0[3] = pack2(a11.x - bf16_hi(a11.x), a11.y - bf16_hi(a11.y));
            ahi1[0] = pack2(b00.x, b00.y); ahi1[1] = pack2(b10.x, b10.y);
            ahi1[2] = pack2(b01.x, b01.y); ahi1[3] = pack2(b11.x, b11.y);
            alo1[0] = pack2(b00.x - bf16_hi(b00.x), b00.y - bf16_hi(b00.y));
            alo1[1] = pack2(b10.x - bf16_hi(b10.x), b10.y - bf16_hi(b10.y));
            alo1[2] = pack2(b01.x - bf16_hi(b01.x), b01.y - bf16_hi(b01.y));
            alo1[3] = pack2(b11.x - bf16_hi(b11.x), b11.y - bf16_hi(b11.y));

            #pragma unroll
            for (int nt = 0; nt < 16; nt++) {
                int nrow = wc * 128 + nt * 8 + g;
                int w0 = nrow * BKW + ks * 8 + tg;
                uint32_t b0h = sBhi[w0], b1h = sBhi[w0 + 4];
                uint32_t b0l = sBlo[w0], b1l = sBlo[w0 + 4];
                mma_bf16(c0[nt], ahi0, b0h, b1h);
                mma_bf16(c0[nt], ahi0, b0l, b1l);
                mma_bf16(c0[nt], alo0, b0h, b1h);
                mma_bf16(c1[nt], ahi1, b0h, b1h);
                mma_bf16(c1[nt], ahi1, b0l, b1l);
                mma_bf16(c1[nt], alo1, b0h, b1h);
            }
        }

        int lr = wr * 32 + g;
        if (wc == 1) {   // residual half: stage relu(val + rb)
            #pragma unroll
            for (int nt = 0; nt < 16; nt++) {
                int col = nt * 8 + tg * 2;
                float rb0 = rb[col], rb1 = rb[col + 1];
                stage[(lr)      * 136 + col]     = fmaxf(c0[nt][0] + rb0, 0.f);
                stage[(lr)      * 136 + col + 1] = fmaxf(c0[nt][1] + rb1, 0.f);
                stage[(lr + 8)  * 136 + col]     = fmaxf(c0[nt][2] + rb0, 0.f);
                stage[(lr + 8)  * 136 + col + 1] = fmaxf(c0[nt][3] + rb1, 0.f);
                stage[(lr + 16) * 136 + col]     = fmaxf(c1[nt][0] + rb0, 0.f);
                stage[(lr + 16) * 136 + col + 1] = fmaxf(c1[nt][1] + rb1, 0.f);
                stage[(lr + 24) * 136 + col]     = fmaxf(c1[nt][2] + rb0, 0.f);
                stage[(lr + 24) * 136 + col + 1] = fmaxf(c1[nt][3] + rb1, 0.f);
            }
        }
        __syncthreads();
        if (wc == 0) {   // main half: store packed h + agg0 = b + relu(res)
            #pragma unroll
            for (int nt = 0; nt < 16; nt++) {
                int col = nt * 8 + tg * 2;
                float2 bb = *(const float2*)(b + col);
                #pragma unroll
                for (int f = 0; f < 4; f++) {
                    int r = (f == 0) ? rA0 : (f == 1) ? rA1 : (f == 2) ? rB0 : rB1;
                    bool ok = (f == 0) ? okA0 : (f == 1) ? okA1 : (f == 2) ? okB0 : okB1;
                    if (!ok) continue;
                    const float* cc = (f < 2) ? c0[nt] : c1[nt];
                    float v0 = (f & 1) ? cc[2] : cc[0];
                    float v1 = (f & 1) ? cc[3] : cc[1];
                    int srow = lr + ((f & 1) ? 8 : 0) + ((f >> 1) ? 16 : 0);
                    g_h16[(size_t)r * 64 + (col >> 1)] = packh2(v0, v1);
                    float2 ag;
                    ag.x = bb.x + stage[srow * 136 + col];
                    ag.y = bb.y + stage[srow * 136 + col + 1];
                    *(float2*)(g_agg + (size_t)r * D + col) = ag;
                }
            }
        }
    }
}

// ---------------- fused: CSR aggregate (fp16 h) + BN stats + grid-sync + normalize ----------------
__global__ void __launch_bounds__(256, 4) k_aggnorm(
    const float* __restrict__ gamma, const float* __restrict__ beta,
    float* __restrict__ out, int N, int nwarps)
{
    __shared__ float ss[8][128];
    __shared__ float sq[8][128];
    __shared__ float ssc[128], ssh[128];
    int wid = threadIdx.x >> 5, lane = threadIdx.x & 31;
    int gw = blockIdx.x * 8 + wid;
    float4 bs = make_float4(0.f, 0.f, 0.f, 0.f);
    float4 bq = make_float4(0.f, 0.f, 0.f, 0.f);

    for (int d = gw; d < N; d += nwarps) {
        int beg = g_roff[d], end = g_roff[d + 1];
        float di = g_dinv[d];
        uint2 hr = *(const uint2*)(g_h16 + (size_t)d * 64 + lane * 2);
        float2 h01 = __half22float2(*reinterpret_cast<__half2*>(&hr.x));
        float2 h23 = __half22float2(*reinterpret_cast<__half2*>(&hr.y));
        float4 acc;
        acc.x = di * h01.x; acc.y = di * h01.y;
        acc.z = di * h23.x; acc.w = di * h23.y;
        for (int j = beg; j < end; j++) {
            int s = g_srcs[j];
            float ds = g_dinv[s];
            uint2 ur = *(const uint2*)(g_h16 + (size_t)s * 64 + lane * 2);
            float2 u01 = __half22float2(*reinterpret_cast<__half2*>(&ur.x));
            float2 u23 = __half22float2(*reinterpret_cast<__half2*>(&ur.y));
            acc.x += ds * u01.x; acc.y += ds * u01.y;
            acc.z += ds * u23.x; acc.w += ds * u23.y;
        }
        float4* ap = (float4*)(g_agg + (size_t)d * D + lane * 4);
        float4 v = *ap;
        v.x += acc.x * di; v.y += acc.y * di;
        v.z += acc.z * di; v.w += acc.w * di;
        *ap = v;
        bs.x += v.x; bs.y += v.y; bs.z += v.z; bs.w += v.w;
        bq.x += v.x * v.x; bq.y += v.y * v.y;
        bq.z += v.z * v.z; bq.w += v.w * v.w;
    }
    *(float4*)&ss[wid][lane * 4] = bs;
    *(float4*)&sq[wid][lane * 4] = bq;
    __syncthreads();
    int col = threadIdx.x & 127;
    if (threadIdx.x < 128) {
        float s = 0.f;
        #pragma unroll
        for (int w = 0; w < 8; w++) s += ss[w][col];
        atomicAdd(&g_sum[col], s);
    } else {
        float s = 0.f;
        #pragma unroll
        for (int w = 0; w < 8; w++) s += sq[w][col];
        atomicAdd(&g_sumsq[col], s);
    }
    __threadfence();
    __syncthreads();

    // ---- grid barrier (all blocks resident by construction) ----
    if (threadIdx.x == 0) {
        atomicAdd(&g_barrier, 1u);
        while (*((volatile unsigned int*)&g_barrier) < (unsigned int)gridDim.x) { }
    }
    __syncthreads();
    __threadfence();

    // ---- BN finalize (per block) ----
    if (threadIdx.x < 128) {
        float inv_n = 1.0f / (float)N;
        float mean = g_sum[threadIdx.x] * inv_n;
        float var = fmaxf(g_sumsq[threadIdx.x] * inv_n - mean * mean, 0.0f);
        float sc = rsqrtf(var + 1e-5f) * gamma[threadIdx.x];
        ssc[threadIdx.x] = sc;
        ssh[threadIdx.x] = beta[threadIdx.x] - mean * sc;
    }
    __syncthreads();

    // ---- normalize the same rows (L2-hot) ----
    float4 sc0 = *(const float4*)&ssc[lane * 4];
    float4 sh0 = *(const float4*)&ssh[lane * 4];
    for (int d = gw; d < N; d += nwarps) {
        float4 v = *(const float4*)(g_agg + (size_t)d * D + lane * 4);
        float4 o;
        o.x = v.x * sc0.x + sh0.x;
        o.y = v.y * sc0.y + sh0.y;
        o.z = v.z * sc0.z + sh0.z;
        o.w = v.w * sc0.w + sh0.w;
        *(float4*)(out + (size_t)d * D + lane * 4) = o;
    }
}

extern "C" void kernel_launch(void* const* d_in, const int* in_sizes, int n_in,
                              void* d_out, int out_size) {
    const float* x     = (const float*)d_in[0];
    const int*   ei32  = (const int*)d_in[1];
    const float* W     = (const float*)d_in[2];
    const float* b     = (const float*)d_in[3];
    const float* rW    = (const float*)d_in[4];
    const float* rb    = (const float*)d_in[5];
    const float* gamma = (const float*)d_in[6];
    const float* beta  = (const float*)d_in[7];
    float* out = (float*)d_out;

    int N = in_sizes[0] / D;
    int E = in_sizes[1] / 2;
    int nblk = (N + SCAN_B - 1) / SCAN_B;
    int ntiles = (N + 127) / 128;
    int gemm_grid = ntiles < 148 ? ntiles : 148;

    cudaFuncSetAttribute(k_gemm_mma, cudaFuncAttributeMaxDynamicSharedMemorySize, SMEM_MMA);

    cudaStream_t s2;
    cudaStreamCreateWithFlags(&s2, cudaStreamNonBlocking);
    cudaEvent_t evFork, evJoin;
    cudaEventCreateWithFlags(&evFork, cudaEventDisableTiming);
    cudaEventCreateWithFlags(&evJoin, cudaEventDisableTiming);

    // fork at t=0: s2 runs zero + CSR build; main runs prep -> GEMM
    cudaEventRecord(evFork, 0);
    cudaStreamWaitEvent(s2, evFork, 0);

    k_zero<<<(N + 255) / 256, 256, 0, s2>>>(ei32, E, N);
    k_hist<<<(E + 255) / 256, 256, 0, s2>>>(ei32, E);
    k_scan1<<<nblk, SCAN_B, 0, s2>>>(N);
    k_scan2<<<1, 1024, 0, s2>>>(nblk, N);
    k_scan3<<<nblk, SCAN_B, 0, s2>>>(N);
    k_fill<<<(E + 255) / 256, 256, 0, s2>>>(ei32, E);
    cudaEventRecord(evJoin, s2);

    k_prep<<<64, 256>>>(W, rW);
    k_gemm_mma<<<gemm_grid, 256, SMEM_MMA>>>(x, b, rb, N, ntiles);

    cudaStreamWaitEvent(0, evJoin, 0);
    k_aggnorm<<<AGG_BLOCKS, 256>>>(gamma, beta, out, N, AGG_BLOCKS * 8);

    cudaEventDestroy(evFork);
    cudaEventDestroy(evJoin);
    cudaStreamDestroy(s2);
}

// round 17
// speedup vs baseline: 1.1314x; 1.0447x over previous
#include <cuda_runtime.h>
#include <cuda_bf16.h>
#include <cuda_fp16.h>
#include <cstdint>

#define D 128
#define MAXN 100000
#define MAXE 1000000
#define SCAN_B 256
#define MAXBLK ((MAXN + SCAN_B - 1) / SCAN_B)
#define BKW 68                 // B row stride in 32-bit words (64 data + 4 pad)
#define AGG_BLOCKS 592         // 148 SMs x 4 resident blocks (guaranteed one wave)

// ---------------- device scratch ----------------
__device__ __align__(16) uint32_t g_h16[(size_t)MAXN * (D / 2)];  // h packed as half2
__device__ __align__(16) float g_agg[(size_t)MAXN * D];   // b + relu(res), then final y
__device__ __align__(16) float g_dinv[MAXN];
__device__ __align__(16) float g_sum[D];
__device__ __align__(16) float g_sumsq[D];
__device__ int g_cnt[MAXN];
__device__ int g_roff[MAXN + 1];
__device__ int g_wcur[MAXN];
__device__ int g_srcs[MAXE];
__device__ int g_bsum[MAXBLK];
__device__ int g_is64;
__device__ unsigned int g_barrier;
// B operand images (fp16x2 words): B = Bhi + Blo exactly to 2^-22.
// [n=256][kword=68]; n<128 -> W col n, else res_W col n-128
__device__ __align__(16) uint32_t g_Bw_hi[256 * BKW];
__device__ __align__(16) uint32_t g_Bw_lo[256 * BKW];

__device__ __forceinline__ int ld_idx(const int* __restrict__ ei32, size_t pos, int is64) {
    return is64 ? ei32[pos << 1] : ei32[pos];
}
__device__ __forceinline__ uint32_t packh2(float a, float b) {
    __half2 t = __floats2half2_rn(a, b);
    return *reinterpret_cast<uint32_t*>(&t);
}
__device__ __forceinline__ float h16_hi(float v) {
    return __half2float(__float2half_rn(v));
}
__device__ __forceinline__ void mma_f16(float* c, const uint32_t* a, uint32_t b0, uint32_t b1) {
    asm volatile(
        "mma.sync.aligned.m16n8k16.row.col.f32.f16.f16.f32 "
        "{%0,%1,%2,%3}, {%4,%5,%6,%7}, {%8,%9}, {%0,%1,%2,%3};"
        : "+f"(c[0]), "+f"(c[1]), "+f"(c[2]), "+f"(c[3])
        : "r"(a[0]), "r"(a[1]), "r"(a[2]), "r"(a[3]), "r"(b0), "r"(b1));
}

// ---------------- K_prep (main): B hi/lo fp16 images (GEMM's sole dependency) ----------------
__global__ void k_prep(const float* __restrict__ W, const float* __restrict__ rW) {
    int t = blockIdx.x * blockDim.x + threadIdx.x;   // 16384 threads
    if (t >= 256 * 64) return;
    int n = t >> 6, kw = t & 63;
    const float* src = (n < 128) ? W : rW;
    int col = n & 127;
    float v0 = src[(size_t)(2 * kw) * D + col];
    float v1 = src[(size_t)(2 * kw + 1) * D + col];
    float h0 = h16_hi(v0), h1 = h16_hi(v1);
    g_Bw_hi[n * BKW + kw] = packh2(v0, v1);
    g_Bw_lo[n * BKW + kw] = packh2(v0 - h0, v1 - h1);
    if (kw < 4) { g_Bw_hi[n * BKW + 64 + kw] = 0; g_Bw_lo[n * BKW + 64 + kw] = 0; }
}

// ---------------- K_zero (s2): counters/sums init + dtype-detect ----------------
__global__ void k_zero(const int* __restrict__ ei32, int E, int N) {
    int i = blockIdx.x * blockDim.x + threadIdx.x;
    if (i < N) g_cnt[i] = 0;
    if (i < D) { g_sum[i] = 0.0f; g_sumsq[i] = 0.0f; }
    if (i == 0) { g_is64 = 1; g_barrier = 0u; }
    __threadfence();
    if (i < E && i < 1024) {
        if (ei32[2 * i + 1] != 0) g_is64 = 0;
    }
}

// ---------------- CSR build ----------------
__global__ void k_hist(const int* __restrict__ ei32, int E) {
    int e = blockIdx.x * blockDim.x + threadIdx.x;
    if (e >= E) return;
    int is64 = g_is64;
    atomicAdd(&g_cnt[ld_idx(ei32, (size_t)E + e, is64)], 1);
}

__global__ void __launch_bounds__(SCAN_B) k_scan1(int N) {
    __shared__ int red[SCAN_B / 32];
    int i = blockIdx.x * SCAN_B + threadIdx.x;
    int v = (i < N) ? g_cnt[i] : 0;
    #pragma unroll
    for (int o = 16; o > 0; o >>= 1) v += __shfl_down_sync(0xffffffff, v, o);
    int warp = threadIdx.x >> 5, lane = threadIdx.x & 31;
    if (lane == 0) red[warp] = v;
    __syncthreads();
    if (warp == 0) {
        int s = (lane < SCAN_B / 32) ? red[lane] : 0;
        #pragma unroll
        for (int o = 4; o > 0; o >>= 1) s += __shfl_down_sync(0xffffffff, s, o);
        if (lane == 0) g_bsum[blockIdx.x] = s;
    }
}

__global__ void __launch_bounds__(1024) k_scan2(int nblk, int N) {
    __shared__ int sh[1024];
    int t = threadIdx.x;
    int v = (t < nblk) ? g_bsum[t] : 0;
    sh[t] = v;
    __syncthreads();
    for (int off = 1; off < 1024; off <<= 1) {
        int u = (t >= off) ? sh[t - off] : 0;
        __syncthreads();
        sh[t] += u;
        __syncthreads();
    }
    if (t < nblk) g_bsum[t] = sh[t] - v;
    if (t == 0) g_roff[N] = sh[1023];
}

__global__ void __launch_bounds__(SCAN_B) k_scan3(int N) {
    __shared__ int wsum[SCAN_B / 32];
    int i = blockIdx.x * SCAN_B + threadIdx.x;
    int c = (i < N) ? g_cnt[i] : 0;
    int lane = threadIdx.x & 31, warp = threadIdx.x >> 5;
    int s = c;
    #pragma unroll
    for (int o = 1; o < 32; o <<= 1) {
        int u = __shfl_up_sync(0xffffffff, s, o);
        if (lane >= o) s += u;
    }
    if (lane == 31) wsum[warp] = s;
    __syncthreads();
    if (warp == 0) {
        int w = (lane < SCAN_B / 32) ? wsum[lane] : 0;
        #pragma unroll
        for (int o = 1; o < SCAN_B / 32; o <<= 1) {
            int u = __shfl_up_sync(0xffffffff, w, o);
            if (lane >= o) w += u;
        }
        if (lane < SCAN_B / 32) wsum[lane] = w;
    }
    __syncthreads();
    int excl = s - c + (warp > 0 ? wsum[warp - 1] : 0) + g_bsum[blockIdx.x];
    if (i < N) {
        g_roff[i] = excl;
        g_wcur[i] = excl;
        g_dinv[i] = rsqrtf((float)c + 1.0f);
    }
}

__global__ void k_fill(const int* __restrict__ ei32, int E) {
    int e = blockIdx.x * blockDim.x + threadIdx.x;
    if (e >= E) return;
    int is64 = g_is64;
    int s = ld_idx(ei32, (size_t)e, is64);
    int d = ld_idx(ei32, (size_t)E + e, is64);
    g_srcs[atomicAdd(&g_wcur[d], 1)] = s;
}

// ---------------- persistent mma.sync fused dual GEMM (fp16 2-term split) ----------------
// Tile: 128 rows x 256 cols; 8 warps: wr = wid&3 (32-row band, TWO m16 frags
// sharing each B load), wc = wid>>2 (128-col half). A rounded to fp16 once;
// B exact via Bhi+Blo -> 2 MMAs per (frag, nt). K=128.
// Writes h packed fp16x2 and agg0 = b + relu(res). Depends only on k_prep.
#define S_BHI 0
#define S_BLO 69632
#define S_STAGE 139264          // float stage[128][136]
#define SMEM_MMA (S_STAGE + 128 * 136 * 4)

__global__ void __launch_bounds__(256, 1) k_gemm_mma(
    const float* __restrict__ x, const float* __restrict__ b,
    const float* __restrict__ rb, int N, int ntiles)
{
    extern __shared__ char smem[];
    uint32_t* sBhi = (uint32_t*)(smem + S_BHI);
    uint32_t* sBlo = (uint32_t*)(smem + S_BLO);
    float* stage = (float*)(smem + S_STAGE);

    const int tid = threadIdx.x;
    const int wid = tid >> 5, lane = tid & 31;
    const int wr = wid & 3, wc = wid >> 2;
    const int g = lane >> 2, tg = lane & 3;

    {
        const uint4* sh = (const uint4*)g_Bw_hi;
        const uint4* sl = (const uint4*)g_Bw_lo;
        uint4* dh = (uint4*)sBhi;
        uint4* dl = (uint4*)sBlo;
        #pragma unroll
        for (int i = 0; i < 17; i++) {
            int idx = tid + i * 256;
            dh[idx] = sh[idx];
            dl[idx] = sl[idx];
        }
    }
    __syncthreads();

    for (int tile = blockIdx.x; tile < ntiles; tile += gridDim.x) {
        __syncthreads();

        const int base = tile * 128 + wr * 32;
        const int rA0 = base + g,      rA1 = base + 8 + g;
        const int rB0 = base + 16 + g, rB1 = base + 24 + g;
        const bool okA0 = rA0 < N, okA1 = rA1 < N, okB0 = rB0 < N, okB1 = rB1 < N;
        const float* xA0 = x + (size_t)rA0 * D;
        const float* xA1 = x + (size_t)rA1 * D;
        const float* xB0 = x + (size_t)rB0 * D;
        const float* xB1 = x + (size_t)rB1 * D;

        float c0[16][4], c1[16][4];
        #pragma unroll
        for (int i = 0; i < 16; i++)
            #pragma unroll
            for (int j = 0; j < 4; j++) { c0[i][j] = 0.f; c1[i][j] = 0.f; }

        #pragma unroll
        for (int ks = 0; ks < 8; ks++) {
            int k0 = ks * 16 + tg * 2;
            float2 z = make_float2(0.f, 0.f);
            float2 a00 = okA0 ? *(const float2*)(xA0 + k0)     : z;
            float2 a10 = okA1 ? *(const float2*)(xA1 + k0)     : z;
            float2 a01 = okA0 ? *(const float2*)(xA0 + k0 + 8) : z;
            float2 a11 = okA1 ? *(const float2*)(xA1 + k0 + 8) : z;
            float2 b00 = okB0 ? *(const float2*)(xB0 + k0)     : z;
            float2 b10 = okB1 ? *(const float2*)(xB1 + k0)     : z;
            float2 b01 = okB0 ? *(const float2*)(xB0 + k0 + 8) : z;
            float2 b11 = okB1 ? *(const float2*)(xB1 + k0 + 8) : z;
            uint32_t ahi0[4], ahi1[4];
            ahi0[0] = packh2(a00.x, a00.y);
            ahi0[1] = packh2(a10.x, a10.y);
            ahi0[2] = packh2(a01.x, a01.y);
            ahi0[3] = packh2(a11.x, a11.y);
            ahi1[0] = packh2(b00.x, b00.y);
            ahi1[1] = packh2(b10.x, b10.y);
            ahi1[2] = packh2(b01.x, b01.y);
            ahi1[3] = packh2(b11.x, b11.y);

            #pragma unroll
            for (int nt = 0; nt < 16; nt++) {
                int nrow = wc * 128 + nt * 8 + g;
                int w0 = nrow * BKW + ks * 8 + tg;
                uint32_t b0h = sBhi[w0], b1h = sBhi[w0 + 4];
                uint32_t b0l = sBlo[w0], b1l = sBlo[w0 + 4];
                mma_f16(c0[nt], ahi0, b0h, b1h);
                mma_f16(c0[nt], ahi0, b0l, b1l);
                mma_f16(c1[nt], ahi1, b0h, b1h);
                mma_f16(c1[nt], ahi1, b0l, b1l);
            }
        }

        int lr = wr * 32 + g;
        if (wc == 1) {   // residual half: stage relu(val + rb)
            #pragma unroll
            for (int nt = 0; nt < 16; nt++) {
                int col = nt * 8 + tg * 2;
                float rb0 = rb[col], rb1 = rb[col + 1];
                stage[(lr)      * 136 + col]     = fmaxf(c0[nt][0] + rb0, 0.f);
                stage[(lr)      * 136 + col + 1] = fmaxf(c0[nt][1] + rb1, 0.f);
                stage[(lr + 8)  * 136 + col]     = fmaxf(c0[nt][2] + rb0, 0.f);
                stage[(lr + 8)  * 136 + col + 1] = fmaxf(c0[nt][3] + rb1, 0.f);
                stage[(lr + 16) * 136 + col]     = fmaxf(c1[nt][0] + rb0, 0.f);
                stage[(lr + 16) * 136 + col + 1] = fmaxf(c1[nt][1] + rb1, 0.f);
                stage[(lr + 24) * 136 + col]     = fmaxf(c1[nt][2] + rb0, 0.f);
                stage[(lr + 24) * 136 + col + 1] = fmaxf(c1[nt][3] + rb1, 0.f);
            }
        }
        __syncthreads();
        if (wc == 0) {   // main half: store packed h + agg0 = b + relu(res)
            #pragma unroll
            for (int nt = 0; nt < 16; nt++) {
                int col = nt * 8 + tg * 2;
                float2 bb = *(const float2*)(b + col);
                #pragma unroll
                for (int f = 0; f < 4; f++) {
                    int r = (f == 0) ? rA0 : (f == 1) ? rA1 : (f == 2) ? rB0 : rB1;
                    bool ok = (f == 0) ? okA0 : (f == 1) ? okA1 : (f == 2) ? okB0 : okB1;
                    if (!ok) continue;
                    const float* cc = (f < 2) ? c0[nt] : c1[nt];
                    float v0 = (f & 1) ? cc[2] : cc[0];
                    float v1 = (f & 1) ? cc[3] : cc[1];
                    int srow = lr + ((f & 1) ? 8 : 0) + ((f >> 1) ? 16 : 0);
                    g_h16[(size_t)r * 64 + (col >> 1)] = packh2(v0, v1);
                    float2 ag;
                    ag.x = bb.x + stage[srow * 136 + col];
                    ag.y = bb.y + stage[srow * 136 + col + 1];
                    *(float2*)(g_agg + (size_t)r * D + col) = ag;
                }
            }
        }
    }
}

// ---------------- fused: CSR aggregate (fp16 h) + BN stats + grid-sync + normalize ----------------
__global__ void __launch_bounds__(256, 4) k_aggnorm(
    const float* __restrict__ gamma, const float* __restrict__ beta,
    float* __restrict__ out, int N, int nwarps)
{
    __shared__ float ss[8][128];
    __shared__ float sq[8][128];
    __shared__ float ssc[128], ssh[128];
    int wid = threadIdx.x >> 5, lane = threadIdx.x & 31;
    int gw = blockIdx.x * 8 + wid;
    float4 bs = make_float4(0.f, 0.f, 0.f, 0.f);
    float4 bq = make_float4(0.f, 0.f, 0.f, 0.f);

    for (int d = gw; d < N; d += nwarps) {
        int beg = g_roff[d], end = g_roff[d + 1];
        float di = g_dinv[d];
        uint2 hr = *(const uint2*)(g_h16 + (size_t)d * 64 + lane * 2);
        float2 h01 = __half22float2(*reinterpret_cast<__half2*>(&hr.x));
        float2 h23 = __half22float2(*reinterpret_cast<__half2*>(&hr.y));
        float4 acc;
        acc.x = di * h01.x; acc.y = di * h01.y;
        acc.z = di * h23.x; acc.w = di * h23.y;
        for (int j = beg; j < end; j++) {
            int s = g_srcs[j];
            float ds = g_dinv[s];
            uint2 ur = *(const uint2*)(g_h16 + (size_t)s * 64 + lane * 2);
            float2 u01 = __half22float2(*reinterpret_cast<__half2*>(&ur.x));
            float2 u23 = __half22float2(*reinterpret_cast<__half2*>(&ur.y));
            acc.x += ds * u01.x; acc.y += ds * u01.y;
            acc.z += ds * u23.x; acc.w += ds * u23.y;
        }
        float4* ap = (float4*)(g_agg + (size_t)d * D + lane * 4);
        float4 v = *ap;
        v.x += acc.x * di; v.y += acc.y * di;
        v.z += acc.z * di; v.w += acc.w * di;
        *ap = v;
        bs.x += v.x; bs.y += v.y; bs.z += v.z; bs.w += v.w;
        bq.x += v.x * v.x; bq.y += v.y * v.y;
        bq.z += v.z * v.z; bq.w += v.w * v.w;
    }
    *(float4*)&ss[wid][lane * 4] = bs;
    *(float4*)&sq[wid][lane * 4] = bq;
    __syncthreads();
    int col = threadIdx.x & 127;
    if (threadIdx.x < 128) {
        float s = 0.f;
        #pragma unroll
        for (int w = 0; w < 8; w++) s += ss[w][col];
        atomicAdd(&g_sum[col], s);
    } else {
        float s = 0.f;
        #pragma unroll
        for (int w = 0; w < 8; w++) s += sq[w][col];
        atomicAdd(&g_sumsq[col], s);
    }
    __threadfence();
    __syncthreads();

    // ---- grid barrier (all blocks resident by construction) ----
    if (threadIdx.x == 0) {
        atomicAdd(&g_barrier, 1u);
        while (*((volatile unsigned int*)&g_barrier) < (unsigned int)gridDim.x) { }
    }
    __syncthreads();
    __threadfence();

    // ---- BN finalize (per block) ----
    if (threadIdx.x < 128) {
        float inv_n = 1.0f / (float)N;
        float mean = g_sum[threadIdx.x] * inv_n;
        float var = fmaxf(g_sumsq[threadIdx.x] * inv_n - mean * mean, 0.0f);
        float sc = rsqrtf(var + 1e-5f) * gamma[threadIdx.x];
        ssc[threadIdx.x] = sc;
        ssh[threadIdx.x] = beta[threadIdx.x] - mean * sc;
    }
    __syncthreads();

    // ---- normalize the same rows (L2-hot) ----
    float4 sc0 = *(const float4*)&ssc[lane * 4];
    float4 sh0 = *(const float4*)&ssh[lane * 4];
    for (int d = gw; d < N; d += nwarps) {
        float4 v = *(const float4*)(g_agg + (size_t)d * D + lane * 4);
        float4 o;
        o.x = v.x * sc0.x + sh0.x;
        o.y = v.y * sc0.y + sh0.y;
        o.z = v.z * sc0.z + sh0.z;
        o.w = v.w * sc0.w + sh0.w;
        *(float4*)(out + (size_t)d * D + lane * 4) = o;
    }
}

extern "C" void kernel_launch(void* const* d_in, const int* in_sizes, int n_in,
                              void* d_out, int out_size) {
    const float* x     = (const float*)d_in[0];
    const int*   ei32  = (const int*)d_in[1];
    const float* W     = (const float*)d_in[2];
    const float* b     = (const float*)d_in[3];
    const float* rW    = (const float*)d_in[4];
    const float* rb    = (const float*)d_in[5];
    const float* gamma = (const float*)d_in[6];
    const float* beta  = (const float*)d_in[7];
    float* out = (float*)d_out;

    int N = in_sizes[0] / D;
    int E = in_sizes[1] / 2;
    int nblk = (N + SCAN_B - 1) / SCAN_B;
    int ntiles = (N + 127) / 128;
    int gemm_grid = ntiles < 148 ? ntiles : 148;

    cudaFuncSetAttribute(k_gemm_mma, cudaFuncAttributeMaxDynamicSharedMemorySize, SMEM_MMA);

    cudaStream_t s2;
    cudaStreamCreateWithFlags(&s2, cudaStreamNonBlocking);
    cudaEvent_t evFork, evJoin;
    cudaEventCreateWithFlags(&evFork, cudaEventDisableTiming);
    cudaEventCreateWithFlags(&evJoin, cudaEventDisableTiming);

    // fork at t=0: s2 runs zero + CSR build; main runs prep -> GEMM
    cudaEventRecord(evFork, 0);
    cudaStreamWaitEvent(s2, evFork, 0);

    k_zero<<<(N + 255) / 256, 256, 0, s2>>>(ei32, E, N);
    k_hist<<<(E + 255) / 256, 256, 0, s2>>>(ei32, E);
    k_scan1<<<nblk, SCAN_B, 0, s2>>>(N);
    k_scan2<<<1, 1024, 0, s2>>>(nblk, N);
    k_scan3<<<nblk, SCAN_B, 0, s2>>>(N);
    k_fill<<<(E + 255) / 256, 256, 0, s2>>>(ei32, E);
    cudaEventRecord(evJoin, s2);

    k_prep<<<64, 256>>>(W, rW);
    k_gemm_mma<<<gemm_grid, 256, SMEM_MMA>>>(x, b, rb, N, ntiles);

    cudaStreamWaitEvent(0, evJoin, 0);
    k_aggnorm<<<AGG_BLOCKS, 256>>>(gamma, beta, out, N, AGG_BLOCKS * 8);

    cudaEventDestroy(evFork);
    cudaEventDestroy(evJoin);
    cudaStreamDestroy(s2);
}